// round 6
// baseline (speedup 1.0000x reference)
#include <cuda_runtime.h>
#include <cuda_fp16.h>
#include <cstdint>

// ============================================================================
// interactionModule_nonParametric_torque: per-edge MLP (4->128->128->128->1)
// + segment-mean over dst + node velocity.
//
// compute_100 target (no tcgen05) -> classic mma.sync m16n8k16 HMMA.
// R6: split per-edge feature computation (gathers + sincos) into its own
// kernel writing packed-fp16 features in A-fragment order to a global
// scratch buffer; gnn_main becomes pure GEMM+epilogue with two coalesced
// LDG.32 per tile. __sincosf (MUFU) replaces accurate sincosf.
// ============================================================================

#define H 128
#define NMAX 50000
#define EMAX 800000
#define EPADMAX ((EMAX + 15) & ~15)
#define NWARPS 6            // warps per CTA

__device__ float g_sums[NMAX];
__device__ int   g_cnt[NMAX];
__device__ uint2 g_feat[EPADMAX];   // per-edge {h2(f0,f1), h2(f2,f3)}

// ---- SMEM layout (bytes) ----
static constexpr int OFF_WB0  = 0;          // 16 j * 32 lanes * 8B      = 4096
static constexpr int OFF_WB1  = 4096;       // 16*8*32*8                 = 32768
static constexpr int OFF_WB2  = 36864;      // 32768
static constexpr int OFF_B0F2 = 69632;      // 16*32*8                   = 4096
static constexpr int OFF_B1F2 = 73728;      // 4096
static constexpr int OFF_B2F2 = 77824;      // 4096
static constexpr int OFF_W3F2 = 81920;      // 4096
static constexpr int SMEM_TOTAL = 86016;

__device__ __forceinline__ void mma16816(float& c0, float& c1, float& c2, float& c3,
                                         uint32_t a0, uint32_t a1, uint32_t a2, uint32_t a3,
                                         uint32_t b0, uint32_t b1) {
    asm volatile(
        "mma.sync.aligned.m16n8k16.row.col.f32.f16.f16.f32 "
        "{%0,%1,%2,%3},{%4,%5,%6,%7},{%8,%9},{%0,%1,%2,%3};"
        : "+f"(c0), "+f"(c1), "+f"(c2), "+f"(c3)
        : "r"(a0), "r"(a1), "r"(a2), "r"(a3), "r"(b0), "r"(b1));
}

__device__ __forceinline__ uint32_t pack_h2(float lo, float hi) {
    __half2 h = __floats2half2_rn(lo, hi);
    return *reinterpret_cast<uint32_t*>(&h);
}

// One hidden layer: 16 n-tiles, processed in independent pairs for ILP.
__device__ __forceinline__ void layer128(float acc[16][4], const uint32_t a[8][4],
                                         const uint2* __restrict__ wb, int lane) {
    #pragma unroll
    for (int jp = 0; jp < 8; jp++) {
        const int j0 = 2 * jp, j1 = 2 * jp + 1;
        float p0 = 0.f, p1 = 0.f, p2 = 0.f, p3 = 0.f;
        float q0 = 0.f, q1 = 0.f, q2 = 0.f, q3 = 0.f;
        #pragma unroll
        for (int ks = 0; ks < 8; ks++) {
            uint2 b0 = wb[(j0 * 8 + ks) * 32 + lane];
            uint2 b1 = wb[(j1 * 8 + ks) * 32 + lane];
            mma16816(p0, p1, p2, p3, a[ks][0], a[ks][1], a[ks][2], a[ks][3], b0.x, b0.y);
            mma16816(q0, q1, q2, q3, a[ks][0], a[ks][1], a[ks][2], a[ks][3], b1.x, b1.y);
        }
        acc[j0][0] = p0; acc[j0][1] = p1; acc[j0][2] = p2; acc[j0][3] = p3;
        acc[j1][0] = q0; acc[j1][1] = q1; acc[j1][2] = q2; acc[j1][3] = q3;
    }
}

// bias + ReLU + f32->f16, register-local C-frag -> A-frag relayout
__device__ __forceinline__ void convert(const float acc[16][4],
                                        const float2* __restrict__ biasf2,
                                        int lane, uint32_t a[8][4]) {
    #pragma unroll
    for (int j = 0; j < 16; j++) {
        float2 bv = biasf2[j * 32 + lane];
        float v0 = fmaxf(acc[j][0] + bv.x, 0.f);
        float v1 = fmaxf(acc[j][1] + bv.y, 0.f);
        float v2 = fmaxf(acc[j][2] + bv.x, 0.f);
        float v3 = fmaxf(acc[j][3] + bv.y, 0.f);
        int ks = j >> 1, h = j & 1;
        a[ks][2 * h + 0] = pack_h2(v0, v1);
        a[ks][2 * h + 1] = pack_h2(v2, v3);
    }
}

// ---- feature kernel: per-edge gather + rotate + trig -> g_feat; also zeros ----
extern "C" __global__ void k_feat(const float* __restrict__ x,
                                  const float* __restrict__ theta,
                                  const int* __restrict__ src,
                                  const int* __restrict__ dst,
                                  int E, int Epad, int N) {
    int i = blockIdx.x * blockDim.x + threadIdx.x;
    if (i < N) { g_sums[i] = 0.f; g_cnt[i] = 0; }
    if (i >= Epad) return;
    uint2 u = make_uint2(0u, 0u);
    if (i < E) {
        int sN = src[i], dN = dst[i];
        float drx = x[2 * dN]     - x[2 * sN];
        float dry = x[2 * dN + 1] - x[2 * sN + 1];
        float ts = theta[sN], td = theta[dN];
        float ss, cs; __sincosf(ts, &ss, &cs);
        float sdt, cdt; __sincosf(td - ts, &sdt, &cdt);
        u.x = pack_h2( drx * cs + dry * ss, -drx * ss + dry * cs);
        u.y = pack_h2(cdt, sdt);
    }
    g_feat[i] = u;
}

extern "C" __global__ void __launch_bounds__(NWARPS * 32, 2)
gnn_main(const float* __restrict__ W0, const float* __restrict__ b0,
         const float* __restrict__ W1, const float* __restrict__ b1,
         const float* __restrict__ W2, const float* __restrict__ b2,
         const float* __restrict__ W3, const float* __restrict__ b3,
         const int* __restrict__ dst, int E, int nWT) {
    extern __shared__ char smem[];
    const int nThr = NWARPS * 32;
    int tid = threadIdx.x;
    int lane = tid & 31;
    int warp = tid >> 5;
    int g = lane >> 2;     // row group 0..7
    int tig = lane & 3;    // thread-in-group

    uint2*  wb0    = (uint2*) (smem + OFF_WB0);
    uint2*  wb1    = (uint2*) (smem + OFF_WB1);
    uint2*  wb2    = (uint2*) (smem + OFF_WB2);
    float2* b0f2   = (float2*)(smem + OFF_B0F2);
    float2* b1f2   = (float2*)(smem + OFF_B1F2);
    float2* b2f2   = (float2*)(smem + OFF_B2F2);
    float2* w3f2   = (float2*)(smem + OFF_W3F2);

    // ---- stage weights in B-fragment order (once per CTA) ----
    for (int i = tid; i < 16 * 32; i += nThr) {
        int jj = i >> 5, ll = i & 31;
        int gg = ll >> 2, tt = ll & 3;
        int c = 8 * jj + gg;
        int k0 = 2 * tt;
        __half h0 = (k0     < 4) ? __float2half_rn(W0[(k0    ) * H + c]) : __half(0.f);
        __half h1 = (k0 + 1 < 4) ? __float2half_rn(W0[(k0 + 1) * H + c]) : __half(0.f);
        uint2 u;
        u.x = ((uint32_t)__half_as_ushort(h0)) | ((uint32_t)__half_as_ushort(h1) << 16);
        u.y = 0u;
        wb0[i] = u;
    }
    for (int i = tid; i < 16 * 8 * 32; i += nThr) {
        int ll = i & 31;
        int ks = (i >> 5) & 7;
        int jj = i >> 8;
        int gg = ll >> 2, tt = ll & 3;
        int c = 8 * jj + gg;
        int k0 = 16 * ks + 2 * tt;
        uint2 u1, u2;
        u1.x = pack_h2(W1[(k0    ) * H + c], W1[(k0 + 1) * H + c]);
        u1.y = pack_h2(W1[(k0 + 8) * H + c], W1[(k0 + 9) * H + c]);
        u2.x = pack_h2(W2[(k0    ) * H + c], W2[(k0 + 1) * H + c]);
        u2.y = pack_h2(W2[(k0 + 8) * H + c], W2[(k0 + 9) * H + c]);
        wb1[i] = u1;
        wb2[i] = u2;
    }
    for (int i = tid; i < 16 * 32; i += nThr) {
        int jj = i >> 5, tt = i & 3;
        int c = 8 * jj + 2 * tt;
        b0f2[i] = make_float2(b0[c], b0[c + 1]);
        b1f2[i] = make_float2(b1[c], b1[c + 1]);
        b2f2[i] = make_float2(b2[c], b2[c + 1]);
        w3f2[i] = make_float2(W3[c], W3[c + 1]);
    }
    __syncthreads();

    float b3v = b3[0];
    const uint32_t* featu = reinterpret_cast<const uint32_t*>(g_feat);

    int warpsTotal = gridDim.x * NWARPS;
    int wgid = blockIdx.x * NWARPS + warp;

    for (int t = wgid; t < nWT; t += warpsTotal) {
        int row0 = t * 16 + g;
        // A0 fragment directly from the precomputed feature buffer
        uint32_t ra0 = (tig < 2) ? featu[row0 * 2 + tig]       : 0u;
        uint32_t ra1 = (tig < 2) ? featu[(row0 + 8) * 2 + tig] : 0u;

        float acc[16][4];
        // ---- L0: single k-step (K rows 4..15 are zero), 2-way interleave ----
        #pragma unroll
        for (int jp = 0; jp < 8; jp++) {
            const int j0 = 2 * jp, j1 = 2 * jp + 1;
            float p0 = 0.f, p1 = 0.f, p2 = 0.f, p3 = 0.f;
            float q0 = 0.f, q1 = 0.f, q2 = 0.f, q3 = 0.f;
            uint2 b0v = wb0[j0 * 32 + lane];
            uint2 b1v = wb0[j1 * 32 + lane];
            mma16816(p0, p1, p2, p3, ra0, ra1, 0u, 0u, b0v.x, b0v.y);
            mma16816(q0, q1, q2, q3, ra0, ra1, 0u, 0u, b1v.x, b1v.y);
            acc[j0][0] = p0; acc[j0][1] = p1; acc[j0][2] = p2; acc[j0][3] = p3;
            acc[j1][0] = q0; acc[j1][1] = q1; acc[j1][2] = q2; acc[j1][3] = q3;
        }

        uint32_t a[8][4];
        convert(acc, b0f2, lane, a);   // relu(.+b0) -> A1
        layer128(acc, a, wb1, lane);   // L1
        convert(acc, b1f2, lane, a);   // relu(.+b1) -> A2
        layer128(acc, a, wb2, lane);   // L2

        // ---- final layer + reduce: m = sum_j relu(h+b2)*W3 + b3 ----
        float plo = 0.f, phi = 0.f;
        #pragma unroll
        for (int j = 0; j < 16; j++) {
            float2 bv = b2f2[j * 32 + lane];
            float2 wv = w3f2[j * 32 + lane];
            plo += fmaxf(acc[j][0] + bv.x, 0.f) * wv.x
                 + fmaxf(acc[j][1] + bv.y, 0.f) * wv.y;
            phi += fmaxf(acc[j][2] + bv.x, 0.f) * wv.x
                 + fmaxf(acc[j][3] + bv.y, 0.f) * wv.y;
        }
        plo += __shfl_xor_sync(0xffffffffu, plo, 1);
        plo += __shfl_xor_sync(0xffffffffu, plo, 2);
        phi += __shfl_xor_sync(0xffffffffu, phi, 1);
        phi += __shfl_xor_sync(0xffffffffu, phi, 2);

        int e = t * 16 + lane;
        int dn = (lane < 16 && e < E) ? dst[e] : -1;
        int dlo = __shfl_sync(0xffffffffu, dn, g);
        int dhi = __shfl_sync(0xffffffffu, dn, g + 8);
        if (tig == 0) {
            if (dlo >= 0) {
                atomicAdd(&g_sums[dlo], plo + b3v);
                atomicAdd(&g_cnt[dlo], 1);
            }
            if (dhi >= 0) {
                atomicAdd(&g_sums[dhi], phi + b3v);
                atomicAdd(&g_cnt[dhi], 1);
            }
        }
    }
}

// ---------------- finalize ----------------
extern "C" __global__ void k_final(const float* __restrict__ theta,
                                   const float* __restrict__ v0p,
                                   float* __restrict__ out, int n) {
    int i = blockIdx.x * blockDim.x + threadIdx.x;
    if (i < n) {
        float v0 = v0p[0];
        float s, c; __sincosf(theta[i], &s, &c);
        out[2 * i]     = v0 * c;
        out[2 * i + 1] = v0 * s;
        out[2 * n + i] = g_sums[i] / fmaxf((float)g_cnt[i], 1.f);
    }
}

// ---------------- launch ----------------
extern "C" void kernel_launch(void* const* d_in, const int* in_sizes, int n_in,
                              void* d_out, int out_size) {
    const float* x     = (const float*)d_in[0];
    const float* theta = (const float*)d_in[1];
    const float* v0    = (const float*)d_in[2];
    const float* W0    = (const float*)d_in[3];
    const float* b0    = (const float*)d_in[4];
    const float* W1    = (const float*)d_in[5];
    const float* b1    = (const float*)d_in[6];
    const float* W2    = (const float*)d_in[7];
    const float* b2    = (const float*)d_in[8];
    const float* W3    = (const float*)d_in[9];
    const float* b3    = (const float*)d_in[10];
    const int*   src   = (const int*)d_in[11];
    const int*   dst   = (const int*)d_in[12];

    int N = in_sizes[1];    // theta element count
    int E = in_sizes[11];   // src element count
    float* out = (float*)d_out;

    cudaFuncSetAttribute(gnn_main, cudaFuncAttributeMaxDynamicSharedMemorySize, SMEM_TOTAL);

    int Epad = (E + 15) & ~15;
    int featThreads = (Epad > N) ? Epad : N;
    k_feat<<<(featThreads + 255) / 256, 256>>>(x, theta, src, dst, E, Epad, N);

    int nWT = Epad / 16;       // 16 edges per warp tile
    int grid = 296;            // 2 CTAs per SM on 148 SMs
    if (grid * NWARPS > nWT) grid = (nWT + NWARPS - 1) / NWARPS;
    gnn_main<<<grid, NWARPS * 32, SMEM_TOTAL>>>(W0, b0, W1, b1, W2, b2, W3, b3,
                                                dst, E, nWT);

    k_final<<<(N + 255) / 256, 256>>>(theta, v0, out, N);
}

// round 7
// speedup vs baseline: 1.0569x; 1.0569x over previous
#include <cuda_runtime.h>
#include <cuda_fp16.h>
#include <cstdint>

// ============================================================================
// interactionModule_nonParametric_torque: per-edge MLP (4->128->128->128->1)
// + segment-mean over dst + node velocity.
//
// compute_100 target (no tcgen05) -> classic mma.sync HMMA.
// R7: gnn_main is tensor-pipe-throughput-bound (rt ~12 cyc/HMMA.16816/SMSP on
// sm_100 legacy path). So: (1) per-edge feature math (MUFU __sincosf + fma)
// moved INTO gnn_main where it issues in tensor stall slots (removes serial
// 17.7us k_feat); A-fragments assembled via shfl.idx, no SMEM staging.
// (2) L0 uses m16n8k8 (real K=4). Weights in SMEM in B-fragment order.
// ============================================================================

#define H 128
#define NMAX 50000
#define NWARPS 6            // warps per CTA

__device__ float g_sums[NMAX];
__device__ int   g_cnt[NMAX];

// ---- SMEM layout (bytes) ----
static constexpr int OFF_WB0  = 0;          // 16 j * 32 lanes * 4B      = 2048
static constexpr int OFF_WB1  = 2048;       // 16*8*32*8                 = 32768
static constexpr int OFF_WB2  = 34816;      // 32768
static constexpr int OFF_B0F2 = 67584;      // 16*32*8                   = 4096
static constexpr int OFF_B1F2 = 71680;      // 4096
static constexpr int OFF_B2F2 = 75776;      // 4096
static constexpr int OFF_W3F2 = 79872;      // 4096
static constexpr int SMEM_TOTAL = 83968;

__device__ __forceinline__ void mma16816(float& c0, float& c1, float& c2, float& c3,
                                         uint32_t a0, uint32_t a1, uint32_t a2, uint32_t a3,
                                         uint32_t b0, uint32_t b1) {
    asm volatile(
        "mma.sync.aligned.m16n8k16.row.col.f32.f16.f16.f32 "
        "{%0,%1,%2,%3},{%4,%5,%6,%7},{%8,%9},{%0,%1,%2,%3};"
        : "+f"(c0), "+f"(c1), "+f"(c2), "+f"(c3)
        : "r"(a0), "r"(a1), "r"(a2), "r"(a3), "r"(b0), "r"(b1));
}

__device__ __forceinline__ void mma16808(float& c0, float& c1, float& c2, float& c3,
                                         uint32_t a0, uint32_t a1, uint32_t b0) {
    asm volatile(
        "mma.sync.aligned.m16n8k8.row.col.f32.f16.f16.f32 "
        "{%0,%1,%2,%3},{%4,%5},{%6},{%0,%1,%2,%3};"
        : "+f"(c0), "+f"(c1), "+f"(c2), "+f"(c3)
        : "r"(a0), "r"(a1), "r"(b0));
}

__device__ __forceinline__ uint32_t pack_h2(float lo, float hi) {
    __half2 h = __floats2half2_rn(lo, hi);
    return *reinterpret_cast<uint32_t*>(&h);
}

// One hidden layer: 16 n-tiles, processed in independent pairs for ILP.
__device__ __forceinline__ void layer128(float acc[16][4], const uint32_t a[8][4],
                                         const uint2* __restrict__ wb, int lane) {
    #pragma unroll
    for (int jp = 0; jp < 8; jp++) {
        const int j0 = 2 * jp, j1 = 2 * jp + 1;
        float p0 = 0.f, p1 = 0.f, p2 = 0.f, p3 = 0.f;
        float q0 = 0.f, q1 = 0.f, q2 = 0.f, q3 = 0.f;
        #pragma unroll
        for (int ks = 0; ks < 8; ks++) {
            uint2 b0 = wb[(j0 * 8 + ks) * 32 + lane];
            uint2 b1 = wb[(j1 * 8 + ks) * 32 + lane];
            mma16816(p0, p1, p2, p3, a[ks][0], a[ks][1], a[ks][2], a[ks][3], b0.x, b0.y);
            mma16816(q0, q1, q2, q3, a[ks][0], a[ks][1], a[ks][2], a[ks][3], b1.x, b1.y);
        }
        acc[j0][0] = p0; acc[j0][1] = p1; acc[j0][2] = p2; acc[j0][3] = p3;
        acc[j1][0] = q0; acc[j1][1] = q1; acc[j1][2] = q2; acc[j1][3] = q3;
    }
}

// bias + ReLU + f32->f16, register-local C-frag -> A-frag relayout
__device__ __forceinline__ void convert(const float acc[16][4],
                                        const float2* __restrict__ biasf2,
                                        int lane, uint32_t a[8][4]) {
    #pragma unroll
    for (int j = 0; j < 16; j++) {
        float2 bv = biasf2[j * 32 + lane];
        float v0 = fmaxf(acc[j][0] + bv.x, 0.f);
        float v1 = fmaxf(acc[j][1] + bv.y, 0.f);
        float v2 = fmaxf(acc[j][2] + bv.x, 0.f);
        float v3 = fmaxf(acc[j][3] + bv.y, 0.f);
        int ks = j >> 1, h = j & 1;
        a[ks][2 * h + 0] = pack_h2(v0, v1);
        a[ks][2 * h + 1] = pack_h2(v2, v3);
    }
}

extern "C" __global__ void __launch_bounds__(NWARPS * 32, 2)
gnn_main(const float* __restrict__ x, const float* __restrict__ theta,
         const float* __restrict__ W0, const float* __restrict__ b0,
         const float* __restrict__ W1, const float* __restrict__ b1,
         const float* __restrict__ W2, const float* __restrict__ b2,
         const float* __restrict__ W3, const float* __restrict__ b3,
         const int* __restrict__ src, const int* __restrict__ dst,
         int E, int nWT) {
    extern __shared__ char smem[];
    const int nThr = NWARPS * 32;
    int tid = threadIdx.x;
    int lane = tid & 31;
    int warp = tid >> 5;
    int g = lane >> 2;     // row group 0..7
    int tig = lane & 3;    // thread-in-group

    uint32_t* wb0  = (uint32_t*)(smem + OFF_WB0);
    uint2*  wb1    = (uint2*)  (smem + OFF_WB1);
    uint2*  wb2    = (uint2*)  (smem + OFF_WB2);
    float2* b0f2   = (float2*) (smem + OFF_B0F2);
    float2* b1f2   = (float2*) (smem + OFF_B1F2);
    float2* b2f2   = (float2*) (smem + OFF_B2F2);
    float2* w3f2   = (float2*) (smem + OFF_W3F2);

    // ---- stage weights in B-fragment order (once per CTA) ----
    // wb0 (m16n8k8 B-frag): rows k=2tt,2tt+1 (real rows k<4), col c=8jj+gg
    for (int i = tid; i < 16 * 32; i += nThr) {
        int jj = i >> 5, ll = i & 31;
        int gg = ll >> 2, tt = ll & 3;
        int c = 8 * jj + gg;
        wb0[i] = (tt < 2) ? pack_h2(W0[(2 * tt) * H + c], W0[(2 * tt + 1) * H + c]) : 0u;
    }
    // wb1/wb2 (m16n8k16 B-frags): 16 n-tiles x 8 k-steps x 32 lanes
    for (int i = tid; i < 16 * 8 * 32; i += nThr) {
        int ll = i & 31;
        int ks = (i >> 5) & 7;
        int jj = i >> 8;
        int gg = ll >> 2, tt = ll & 3;
        int c = 8 * jj + gg;
        int k0 = 16 * ks + 2 * tt;
        uint2 u1, u2;
        u1.x = pack_h2(W1[(k0    ) * H + c], W1[(k0 + 1) * H + c]);
        u1.y = pack_h2(W1[(k0 + 8) * H + c], W1[(k0 + 9) * H + c]);
        u2.x = pack_h2(W2[(k0    ) * H + c], W2[(k0 + 1) * H + c]);
        u2.y = pack_h2(W2[(k0 + 8) * H + c], W2[(k0 + 9) * H + c]);
        wb1[i] = u1;
        wb2[i] = u2;
    }
    // biases + W3 as per-(n-tile,lane) float2
    for (int i = tid; i < 16 * 32; i += nThr) {
        int jj = i >> 5, tt = i & 3;
        int c = 8 * jj + 2 * tt;
        b0f2[i] = make_float2(b0[c], b0[c + 1]);
        b1f2[i] = make_float2(b1[c], b1[c + 1]);
        b2f2[i] = make_float2(b2[c], b2[c + 1]);
        w3f2[i] = make_float2(W3[c], W3[c + 1]);
    }
    __syncthreads();

    float b3v = b3[0];

    int warpsTotal = gridDim.x * NWARPS;
    int wgid = blockIdx.x * NWARPS + warp;

    for (int t = wgid; t < nWT; t += warpsTotal) {
        int e = t * 16 + lane;
        int dn = -1;
        uint32_t fx = 0u, fy = 0u;   // h2(f0,f1), h2(f2,f3) for edge row 'lane'

        // ---- per-edge feature (lanes 0..15), MUFU trig ----
        if (lane < 16 && e < E) {
            int sN = src[e], dN = dst[e];
            float drx = x[2 * dN]     - x[2 * sN];
            float dry = x[2 * dN + 1] - x[2 * sN + 1];
            float ts = theta[sN], td = theta[dN];
            float ss, cs; __sincosf(ts, &ss, &cs);
            float sdt, cdt; __sincosf(td - ts, &sdt, &cdt);
            fx = pack_h2( drx * cs + dry * ss, -drx * ss + dry * cs);
            fy = pack_h2(cdt, sdt);
            dn = dN;
        }

        // A-fragments (m16n8k8) via shuffle: row g / g+8, k-pair tig
        uint32_t vx0 = __shfl_sync(0xffffffffu, fx, g);
        uint32_t vy0 = __shfl_sync(0xffffffffu, fy, g);
        uint32_t vx1 = __shfl_sync(0xffffffffu, fx, g + 8);
        uint32_t vy1 = __shfl_sync(0xffffffffu, fy, g + 8);
        uint32_t ra0 = (tig == 0) ? vx0 : (tig == 1) ? vy0 : 0u;
        uint32_t ra1 = (tig == 0) ? vx1 : (tig == 1) ? vy1 : 0u;

        float acc[16][4];
        // ---- L0: m16n8k8 (real K=4), 2-way n-tile interleave ----
        #pragma unroll
        for (int jp = 0; jp < 8; jp++) {
            const int j0 = 2 * jp, j1 = 2 * jp + 1;
            float p0 = 0.f, p1 = 0.f, p2 = 0.f, p3 = 0.f;
            float q0 = 0.f, q1 = 0.f, q2 = 0.f, q3 = 0.f;
            uint32_t b0v = wb0[j0 * 32 + lane];
            uint32_t b1v = wb0[j1 * 32 + lane];
            mma16808(p0, p1, p2, p3, ra0, ra1, b0v);
            mma16808(q0, q1, q2, q3, ra0, ra1, b1v);
            acc[j0][0] = p0; acc[j0][1] = p1; acc[j0][2] = p2; acc[j0][3] = p3;
            acc[j1][0] = q0; acc[j1][1] = q1; acc[j1][2] = q2; acc[j1][3] = q3;
        }

        uint32_t a[8][4];
        convert(acc, b0f2, lane, a);   // relu(.+b0) -> A1
        layer128(acc, a, wb1, lane);   // L1
        convert(acc, b1f2, lane, a);   // relu(.+b1) -> A2
        layer128(acc, a, wb2, lane);   // L2

        // ---- final layer + reduce: m = sum_j relu(h+b2)*W3 + b3 ----
        float plo = 0.f, phi = 0.f;
        #pragma unroll
        for (int j = 0; j < 16; j++) {
            float2 bv = b2f2[j * 32 + lane];
            float2 wv = w3f2[j * 32 + lane];
            plo += fmaxf(acc[j][0] + bv.x, 0.f) * wv.x
                 + fmaxf(acc[j][1] + bv.y, 0.f) * wv.y;
            phi += fmaxf(acc[j][2] + bv.x, 0.f) * wv.x
                 + fmaxf(acc[j][3] + bv.y, 0.f) * wv.y;
        }
        plo += __shfl_xor_sync(0xffffffffu, plo, 1);
        plo += __shfl_xor_sync(0xffffffffu, plo, 2);
        phi += __shfl_xor_sync(0xffffffffu, phi, 1);
        phi += __shfl_xor_sync(0xffffffffu, phi, 2);
        int dlo = __shfl_sync(0xffffffffu, dn, g);
        int dhi = __shfl_sync(0xffffffffu, dn, g + 8);
        if (tig == 0) {
            if (dlo >= 0) {
                atomicAdd(&g_sums[dlo], plo + b3v);
                atomicAdd(&g_cnt[dlo], 1);
            }
            if (dhi >= 0) {
                atomicAdd(&g_sums[dhi], phi + b3v);
                atomicAdd(&g_cnt[dhi], 1);
            }
        }
    }
}

// ---------------- aux kernels ----------------
extern "C" __global__ void k_zero(int n) {
    int i = blockIdx.x * blockDim.x + threadIdx.x;
    if (i < n) { g_sums[i] = 0.f; g_cnt[i] = 0; }
}

extern "C" __global__ void k_final(const float* __restrict__ theta,
                                   const float* __restrict__ v0p,
                                   float* __restrict__ out, int n) {
    int i = blockIdx.x * blockDim.x + threadIdx.x;
    if (i < n) {
        float v0 = v0p[0];
        float s, c; __sincosf(theta[i], &s, &c);
        out[2 * i]     = v0 * c;
        out[2 * i + 1] = v0 * s;
        out[2 * n + i] = g_sums[i] / fmaxf((float)g_cnt[i], 1.f);
    }
}

// ---------------- launch ----------------
extern "C" void kernel_launch(void* const* d_in, const int* in_sizes, int n_in,
                              void* d_out, int out_size) {
    const float* x     = (const float*)d_in[0];
    const float* theta = (const float*)d_in[1];
    const float* v0    = (const float*)d_in[2];
    const float* W0    = (const float*)d_in[3];
    const float* b0    = (const float*)d_in[4];
    const float* W1    = (const float*)d_in[5];
    const float* b1    = (const float*)d_in[6];
    const float* W2    = (const float*)d_in[7];
    const float* b2    = (const float*)d_in[8];
    const float* W3    = (const float*)d_in[9];
    const float* b3    = (const float*)d_in[10];
    const int*   src   = (const int*)d_in[11];
    const int*   dst   = (const int*)d_in[12];

    int N = in_sizes[1];    // theta element count
    int E = in_sizes[11];   // src element count
    float* out = (float*)d_out;

    cudaFuncSetAttribute(gnn_main, cudaFuncAttributeMaxDynamicSharedMemorySize, SMEM_TOTAL);

    k_zero<<<(N + 255) / 256, 256>>>(N);

    int nWT = (E + 15) / 16;   // 16 edges per warp tile
    int grid = 296;            // 2 CTAs per SM on 148 SMs
    if (grid * NWARPS > nWT) grid = (nWT + NWARPS - 1) / NWARPS;
    gnn_main<<<grid, NWARPS * 32, SMEM_TOTAL>>>(x, theta, W0, b0, W1, b1, W2, b2, W3, b3,
                                                src, dst, E, nWT);

    k_final<<<(N + 255) / 256, 256>>>(theta, v0, out, N);
}

// round 8
// speedup vs baseline: 1.0621x; 1.0048x over previous
#include <cuda_runtime.h>
#include <cuda_fp16.h>
#include <cstdint>

// ============================================================================
// interactionModule_nonParametric_torque: per-edge MLP (4->128->128->128->1)
// + segment-mean over dst + node velocity.
//
// compute_100 target (no tcgen05) -> classic mma.sync HMMA.
// R8: drop k_zero entirely -- __device__ globals start zeroed, and k_final
// resets g_sums/g_cnt after reading (self-cleaning accumulators, graph-safe,
// deterministic). Launch cycle is now [gnn_main, k_final], which also moves
// the ncu-profiled launch onto gnn_main for the next diagnosis round.
// Feature math (MUFU __sincosf) fused in gnn_main; L0 via m16n8k8.
// ============================================================================

#define H 128
#define NMAX 50000
#define NWARPS 6            // warps per CTA

__device__ float g_sums[NMAX];   // zero-initialized at module load
__device__ int   g_cnt[NMAX];    // k_final re-zeros after each use

// ---- SMEM layout (bytes) ----
static constexpr int OFF_WB0  = 0;          // 16 j * 32 lanes * 4B      = 2048
static constexpr int OFF_WB1  = 2048;       // 16*8*32*8                 = 32768
static constexpr int OFF_WB2  = 34816;      // 32768
static constexpr int OFF_B0F2 = 67584;      // 16*32*8                   = 4096
static constexpr int OFF_B1F2 = 71680;      // 4096
static constexpr int OFF_B2F2 = 75776;      // 4096
static constexpr int OFF_W3F2 = 79872;      // 4096
static constexpr int SMEM_TOTAL = 83968;

__device__ __forceinline__ void mma16816(float& c0, float& c1, float& c2, float& c3,
                                         uint32_t a0, uint32_t a1, uint32_t a2, uint32_t a3,
                                         uint32_t b0, uint32_t b1) {
    asm volatile(
        "mma.sync.aligned.m16n8k16.row.col.f32.f16.f16.f32 "
        "{%0,%1,%2,%3},{%4,%5,%6,%7},{%8,%9},{%0,%1,%2,%3};"
        : "+f"(c0), "+f"(c1), "+f"(c2), "+f"(c3)
        : "r"(a0), "r"(a1), "r"(a2), "r"(a3), "r"(b0), "r"(b1));
}

__device__ __forceinline__ void mma16808(float& c0, float& c1, float& c2, float& c3,
                                         uint32_t a0, uint32_t a1, uint32_t b0) {
    asm volatile(
        "mma.sync.aligned.m16n8k8.row.col.f32.f16.f16.f32 "
        "{%0,%1,%2,%3},{%4,%5},{%6},{%0,%1,%2,%3};"
        : "+f"(c0), "+f"(c1), "+f"(c2), "+f"(c3)
        : "r"(a0), "r"(a1), "r"(b0));
}

__device__ __forceinline__ uint32_t pack_h2(float lo, float hi) {
    __half2 h = __floats2half2_rn(lo, hi);
    return *reinterpret_cast<uint32_t*>(&h);
}

// One hidden layer: 16 n-tiles, processed in independent pairs for ILP.
__device__ __forceinline__ void layer128(float acc[16][4], const uint32_t a[8][4],
                                         const uint2* __restrict__ wb, int lane) {
    #pragma unroll
    for (int jp = 0; jp < 8; jp++) {
        const int j0 = 2 * jp, j1 = 2 * jp + 1;
        float p0 = 0.f, p1 = 0.f, p2 = 0.f, p3 = 0.f;
        float q0 = 0.f, q1 = 0.f, q2 = 0.f, q3 = 0.f;
        #pragma unroll
        for (int ks = 0; ks < 8; ks++) {
            uint2 b0 = wb[(j0 * 8 + ks) * 32 + lane];
            uint2 b1 = wb[(j1 * 8 + ks) * 32 + lane];
            mma16816(p0, p1, p2, p3, a[ks][0], a[ks][1], a[ks][2], a[ks][3], b0.x, b0.y);
            mma16816(q0, q1, q2, q3, a[ks][0], a[ks][1], a[ks][2], a[ks][3], b1.x, b1.y);
        }
        acc[j0][0] = p0; acc[j0][1] = p1; acc[j0][2] = p2; acc[j0][3] = p3;
        acc[j1][0] = q0; acc[j1][1] = q1; acc[j1][2] = q2; acc[j1][3] = q3;
    }
}

// bias + ReLU + f32->f16, register-local C-frag -> A-frag relayout
__device__ __forceinline__ void convert(const float acc[16][4],
                                        const float2* __restrict__ biasf2,
                                        int lane, uint32_t a[8][4]) {
    #pragma unroll
    for (int j = 0; j < 16; j++) {
        float2 bv = biasf2[j * 32 + lane];
        float v0 = fmaxf(acc[j][0] + bv.x, 0.f);
        float v1 = fmaxf(acc[j][1] + bv.y, 0.f);
        float v2 = fmaxf(acc[j][2] + bv.x, 0.f);
        float v3 = fmaxf(acc[j][3] + bv.y, 0.f);
        int ks = j >> 1, h = j & 1;
        a[ks][2 * h + 0] = pack_h2(v0, v1);
        a[ks][2 * h + 1] = pack_h2(v2, v3);
    }
}

extern "C" __global__ void __launch_bounds__(NWARPS * 32, 2)
gnn_main(const float* __restrict__ x, const float* __restrict__ theta,
         const float* __restrict__ W0, const float* __restrict__ b0,
         const float* __restrict__ W1, const float* __restrict__ b1,
         const float* __restrict__ W2, const float* __restrict__ b2,
         const float* __restrict__ W3, const float* __restrict__ b3,
         const int* __restrict__ src, const int* __restrict__ dst,
         int E, int nWT) {
    extern __shared__ char smem[];
    const int nThr = NWARPS * 32;
    int tid = threadIdx.x;
    int lane = tid & 31;
    int warp = tid >> 5;
    int g = lane >> 2;     // row group 0..7
    int tig = lane & 3;    // thread-in-group

    uint32_t* wb0  = (uint32_t*)(smem + OFF_WB0);
    uint2*  wb1    = (uint2*)  (smem + OFF_WB1);
    uint2*  wb2    = (uint2*)  (smem + OFF_WB2);
    float2* b0f2   = (float2*) (smem + OFF_B0F2);
    float2* b1f2   = (float2*) (smem + OFF_B1F2);
    float2* b2f2   = (float2*) (smem + OFF_B2F2);
    float2* w3f2   = (float2*) (smem + OFF_W3F2);

    // ---- stage weights in B-fragment order (once per CTA) ----
    // wb0 (m16n8k8 B-frag): rows k=2tt,2tt+1 (real rows k<4), col c=8jj+gg
    for (int i = tid; i < 16 * 32; i += nThr) {
        int jj = i >> 5, ll = i & 31;
        int gg = ll >> 2, tt = ll & 3;
        int c = 8 * jj + gg;
        wb0[i] = (tt < 2) ? pack_h2(W0[(2 * tt) * H + c], W0[(2 * tt + 1) * H + c]) : 0u;
    }
    // wb1/wb2 (m16n8k16 B-frags): 16 n-tiles x 8 k-steps x 32 lanes
    for (int i = tid; i < 16 * 8 * 32; i += nThr) {
        int ll = i & 31;
        int ks = (i >> 5) & 7;
        int jj = i >> 8;
        int gg = ll >> 2, tt = ll & 3;
        int c = 8 * jj + gg;
        int k0 = 16 * ks + 2 * tt;
        uint2 u1, u2;
        u1.x = pack_h2(W1[(k0    ) * H + c], W1[(k0 + 1) * H + c]);
        u1.y = pack_h2(W1[(k0 + 8) * H + c], W1[(k0 + 9) * H + c]);
        u2.x = pack_h2(W2[(k0    ) * H + c], W2[(k0 + 1) * H + c]);
        u2.y = pack_h2(W2[(k0 + 8) * H + c], W2[(k0 + 9) * H + c]);
        wb1[i] = u1;
        wb2[i] = u2;
    }
    // biases + W3 as per-(n-tile,lane) float2
    for (int i = tid; i < 16 * 32; i += nThr) {
        int jj = i >> 5, tt = i & 3;
        int c = 8 * jj + 2 * tt;
        b0f2[i] = make_float2(b0[c], b0[c + 1]);
        b1f2[i] = make_float2(b1[c], b1[c + 1]);
        b2f2[i] = make_float2(b2[c], b2[c + 1]);
        w3f2[i] = make_float2(W3[c], W3[c + 1]);
    }
    __syncthreads();

    float b3v = b3[0];

    int warpsTotal = gridDim.x * NWARPS;
    int wgid = blockIdx.x * NWARPS + warp;

    for (int t = wgid; t < nWT; t += warpsTotal) {
        int e = t * 16 + lane;
        int dn = -1;
        uint32_t fx = 0u, fy = 0u;   // h2(f0,f1), h2(f2,f3) for edge row 'lane'

        // ---- per-edge feature (lanes 0..15), MUFU trig ----
        if (lane < 16 && e < E) {
            int sN = src[e], dN = dst[e];
            float drx = x[2 * dN]     - x[2 * sN];
            float dry = x[2 * dN + 1] - x[2 * sN + 1];
            float ts = theta[sN], td = theta[dN];
            float ss, cs; __sincosf(ts, &ss, &cs);
            float sdt, cdt; __sincosf(td - ts, &sdt, &cdt);
            fx = pack_h2( drx * cs + dry * ss, -drx * ss + dry * cs);
            fy = pack_h2(cdt, sdt);
            dn = dN;
        }

        // A-fragments (m16n8k8) via shuffle: row g / g+8, k-pair tig
        uint32_t vx0 = __shfl_sync(0xffffffffu, fx, g);
        uint32_t vy0 = __shfl_sync(0xffffffffu, fy, g);
        uint32_t vx1 = __shfl_sync(0xffffffffu, fx, g + 8);
        uint32_t vy1 = __shfl_sync(0xffffffffu, fy, g + 8);
        uint32_t ra0 = (tig == 0) ? vx0 : (tig == 1) ? vy0 : 0u;
        uint32_t ra1 = (tig == 0) ? vx1 : (tig == 1) ? vy1 : 0u;

        float acc[16][4];
        // ---- L0: m16n8k8 (real K=4), 2-way n-tile interleave ----
        #pragma unroll
        for (int jp = 0; jp < 8; jp++) {
            const int j0 = 2 * jp, j1 = 2 * jp + 1;
            float p0 = 0.f, p1 = 0.f, p2 = 0.f, p3 = 0.f;
            float q0 = 0.f, q1 = 0.f, q2 = 0.f, q3 = 0.f;
            uint32_t b0v = wb0[j0 * 32 + lane];
            uint32_t b1v = wb0[j1 * 32 + lane];
            mma16808(p0, p1, p2, p3, ra0, ra1, b0v);
            mma16808(q0, q1, q2, q3, ra0, ra1, b1v);
            acc[j0][0] = p0; acc[j0][1] = p1; acc[j0][2] = p2; acc[j0][3] = p3;
            acc[j1][0] = q0; acc[j1][1] = q1; acc[j1][2] = q2; acc[j1][3] = q3;
        }

        uint32_t a[8][4];
        convert(acc, b0f2, lane, a);   // relu(.+b0) -> A1
        layer128(acc, a, wb1, lane);   // L1
        convert(acc, b1f2, lane, a);   // relu(.+b1) -> A2
        layer128(acc, a, wb2, lane);   // L2

        // ---- final layer + reduce: m = sum_j relu(h+b2)*W3 + b3 ----
        float plo = 0.f, phi = 0.f;
        #pragma unroll
        for (int j = 0; j < 16; j++) {
            float2 bv = b2f2[j * 32 + lane];
            float2 wv = w3f2[j * 32 + lane];
            plo += fmaxf(acc[j][0] + bv.x, 0.f) * wv.x
                 + fmaxf(acc[j][1] + bv.y, 0.f) * wv.y;
            phi += fmaxf(acc[j][2] + bv.x, 0.f) * wv.x
                 + fmaxf(acc[j][3] + bv.y, 0.f) * wv.y;
        }
        plo += __shfl_xor_sync(0xffffffffu, plo, 1);
        plo += __shfl_xor_sync(0xffffffffu, plo, 2);
        phi += __shfl_xor_sync(0xffffffffu, phi, 1);
        phi += __shfl_xor_sync(0xffffffffu, phi, 2);
        int dlo = __shfl_sync(0xffffffffu, dn, g);
        int dhi = __shfl_sync(0xffffffffu, dn, g + 8);
        if (tig == 0) {
            if (dlo >= 0) {
                atomicAdd(&g_sums[dlo], plo + b3v);
                atomicAdd(&g_cnt[dlo], 1);
            }
            if (dhi >= 0) {
                atomicAdd(&g_sums[dhi], phi + b3v);
                atomicAdd(&g_cnt[dhi], 1);
            }
        }
    }
}

// ---------------- finalize (reads accumulators, then resets them) ----------
extern "C" __global__ void k_final(const float* __restrict__ theta,
                                   const float* __restrict__ v0p,
                                   float* __restrict__ out, int n) {
    int i = blockIdx.x * blockDim.x + threadIdx.x;
    if (i < n) {
        float v0 = v0p[0];
        float s, c; __sincosf(theta[i], &s, &c);
        out[2 * i]     = v0 * c;
        out[2 * i + 1] = v0 * s;
        out[2 * n + i] = g_sums[i] / fmaxf((float)g_cnt[i], 1.f);
        // self-reset for the next invocation (globals start zeroed at load)
        g_sums[i] = 0.f;
        g_cnt[i]  = 0;
    }
}

// ---------------- launch ----------------
extern "C" void kernel_launch(void* const* d_in, const int* in_sizes, int n_in,
                              void* d_out, int out_size) {
    const float* x     = (const float*)d_in[0];
    const float* theta = (const float*)d_in[1];
    const float* v0    = (const float*)d_in[2];
    const float* W0    = (const float*)d_in[3];
    const float* b0    = (const float*)d_in[4];
    const float* W1    = (const float*)d_in[5];
    const float* b1    = (const float*)d_in[6];
    const float* W2    = (const float*)d_in[7];
    const float* b2    = (const float*)d_in[8];
    const float* W3    = (const float*)d_in[9];
    const float* b3    = (const float*)d_in[10];
    const int*   src   = (const int*)d_in[11];
    const int*   dst   = (const int*)d_in[12];

    int N = in_sizes[1];    // theta element count
    int E = in_sizes[11];   // src element count
    float* out = (float*)d_out;

    cudaFuncSetAttribute(gnn_main, cudaFuncAttributeMaxDynamicSharedMemorySize, SMEM_TOTAL);

    int nWT = (E + 15) / 16;   // 16 edges per warp tile
    int grid = 296;            // 2 CTAs per SM on 148 SMs
    if (grid * NWARPS > nWT) grid = (nWT + NWARPS - 1) / NWARPS;
    gnn_main<<<grid, NWARPS * 32, SMEM_TOTAL>>>(x, theta, W0, b0, W1, b1, W2, b2, W3, b3,
                                                src, dst, E, nWT);

    k_final<<<(N + 255) / 256, 256>>>(theta, v0, out, N);
}